// round 12
// baseline (speedup 1.0000x reference)
#include <cuda_runtime.h>
#include <cstdint>

#define EDIM   1024
#define MSLOTS 256
#define NROWS  32768

// Scratch (no allocations -> __device__ globals). P/Rt pre-rounded to tf32.
__device__ float g_P [MSLOTS * EDIM];              // P  = M @ Wq       [slot, e]
__device__ float g_Rt[EDIM * MSLOTS];              // Rt = (M @ Wo^T)^T [e, slot]
__device__ float g_s0[MSLOTS];                     // s0 = M @ bq  (full fp32)
__device__ float g_w [(size_t)NROWS * MSLOTS];     // softmax weights   [row, slot]
__device__ float g_part[8 * MSLOTS * EDIM];        // K-split partials: [mode*4+ks]

// ---------------------------------------------------------------------------
// Helpers
// ---------------------------------------------------------------------------
__device__ __forceinline__ uint32_t smem_u32(const void* p) {
    uint32_t a;
    asm("{ .reg .u64 t; cvta.to.shared.u64 t, %1; cvt.u32.u64 %0, t; }" : "=r"(a) : "l"(p));
    return a;
}
__device__ __forceinline__ void cp16(uint32_t dst, const void* src) {
    asm volatile("cp.async.cg.shared.global [%0], [%1], 16;" :: "r"(dst), "l"(src));
}
#define CP_COMMIT() asm volatile("cp.async.commit_group;" ::: "memory")
#define CP_WAIT(n)  asm volatile("cp.async.wait_group %0;" :: "n"(n) : "memory")

#define LDSM4(r0, r1, r2, r3, addr) \
    asm volatile("ldmatrix.sync.aligned.m8n8.x4.shared.b16 {%0,%1,%2,%3}, [%4];" \
        : "=r"(r0), "=r"(r1), "=r"(r2), "=r"(r3) : "r"(addr))

#define MMA_TF32(c, a, b) \
    asm volatile("mma.sync.aligned.m16n8k8.row.col.f32.tf32.tf32.f32 " \
        "{%0,%1,%2,%3}, {%4,%5,%6,%7}, {%8,%9}, {%0,%1,%2,%3};" \
        : "+f"((c)[0]), "+f"((c)[1]), "+f"((c)[2]), "+f"((c)[3]) \
        : "r"((a)[0]), "r"((a)[1]), "r"((a)[2]), "r"((a)[3]), "r"((b)[0]), "r"((b)[1]))

__device__ __forceinline__ float to_tf32(float v) {
    uint32_t u;
    asm("cvt.rna.tf32.f32 %0, %1;" : "=r"(u) : "f"(v));
    return __uint_as_float(u);
}
__device__ __forceinline__ void cvt_tf32_r(uint32_t& u) {
    asm("cvt.rna.tf32.f32 %0, %0;" : "+r"(u));
}

// Padded K stride (floats): 16 + 4 -> 80B rows, conflict-free ldmatrix
#define LDK 20
// x-residual smem row stride (floats): 128 + 4 pad (16B-aligned rows)
#define LDX 132

// ---------------------------------------------------------------------------
// Precompute partials with K-split x4: z = mode*4 + ks, K window = ks*256..+256
// ---------------------------------------------------------------------------
__global__ __launch_bounds__(256) void precompute_part(
    const float* __restrict__ Mb, const float* __restrict__ Wq,
    const float* __restrict__ Wo)
{
    constexpr int BM = 64, BN = 64, BK = 32;
    __shared__ float As[BK][BM];
    __shared__ float Bs[BK][BN];
    const int mode = blockIdx.z >> 2;
    const int ks   = blockIdx.z & 3;
    const int m0 = blockIdx.y * BM;
    const int n0 = blockIdx.x * BN;
    const int tid = threadIdx.x;
    const int tm = tid >> 4, tn = tid & 15;
    const int kbeg = ks * 256;
    float acc[4][4] = {};

    for (int kb = kbeg; kb < kbeg + 256; kb += BK) {
        {
            int r = tid >> 2, k0 = (tid & 3) * 8;
            float4 v0 = *(const float4*)(Mb + (m0 + r) * EDIM + kb + k0);
            float4 v1 = *(const float4*)(Mb + (m0 + r) * EDIM + kb + k0 + 4);
            As[k0+0][r] = v0.x; As[k0+1][r] = v0.y; As[k0+2][r] = v0.z; As[k0+3][r] = v0.w;
            As[k0+4][r] = v1.x; As[k0+5][r] = v1.y; As[k0+6][r] = v1.z; As[k0+7][r] = v1.w;
        }
        if (mode == 0) {
            int k = tid >> 3, nq = (tid & 7) * 8;
            float4 v0 = *(const float4*)(Wq + (size_t)(kb + k) * EDIM + n0 + nq);
            float4 v1 = *(const float4*)(Wq + (size_t)(kb + k) * EDIM + n0 + nq + 4);
            *(float4*)&Bs[k][nq]     = v0;
            *(float4*)&Bs[k][nq + 4] = v1;
        } else {
            int n = tid >> 2, k0 = (tid & 3) * 8;
            float4 v0 = *(const float4*)(Wo + (size_t)(n0 + n) * EDIM + kb + k0);
            float4 v1 = *(const float4*)(Wo + (size_t)(n0 + n) * EDIM + kb + k0 + 4);
            Bs[k0+0][n] = v0.x; Bs[k0+1][n] = v0.y; Bs[k0+2][n] = v0.z; Bs[k0+3][n] = v0.w;
            Bs[k0+4][n] = v1.x; Bs[k0+5][n] = v1.y; Bs[k0+6][n] = v1.z; Bs[k0+7][n] = v1.w;
        }
        __syncthreads();
        #pragma unroll
        for (int k = 0; k < BK; k++) {
            float a[4], b[4];
            *(float4*)a = *(const float4*)&As[k][tm * 4];
            *(float4*)b = *(const float4*)&Bs[k][tn * 4];
            #pragma unroll
            for (int i = 0; i < 4; i++)
                #pragma unroll
                for (int j = 0; j < 4; j++)
                    acc[i][j] = fmaf(a[i], b[j], acc[i][j]);
        }
        __syncthreads();
    }
    if (mode == 0) {
        float* dst = g_part + (size_t)ks * (MSLOTS * EDIM);
        #pragma unroll
        for (int i = 0; i < 4; i++) {
            int m = m0 + tm * 4 + i;
            *(float4*)(dst + (size_t)m * EDIM + n0 + tn * 4) =
                make_float4(acc[i][0], acc[i][1], acc[i][2], acc[i][3]);
        }
    } else {
        float* dst = g_part + (size_t)(4 + ks) * (MSLOTS * EDIM);
        #pragma unroll
        for (int i = 0; i < 4; i++)
            #pragma unroll
            for (int j = 0; j < 4; j++)
                dst[(size_t)(n0 + tn * 4 + j) * MSLOTS + (m0 + tm * 4 + i)] = acc[i][j];
    }
}

// Sum 4 K-split partials, round to tf32. t < 65536 -> P float4 t; else Rt.
__global__ __launch_bounds__(256) void reduce_pre()
{
    int t = blockIdx.x * 256 + threadIdx.x;      // 0..131071 (float4 index)
    const int NF4 = MSLOTS * EDIM / 4;           // 65536
    int base = (t < NF4) ? 0 : 4;
    int i = (t < NF4) ? t : t - NF4;
    const float4* p0 = (const float4*)(g_part + (size_t)(base + 0) * (MSLOTS * EDIM));
    const float4* p1 = (const float4*)(g_part + (size_t)(base + 1) * (MSLOTS * EDIM));
    const float4* p2 = (const float4*)(g_part + (size_t)(base + 2) * (MSLOTS * EDIM));
    const float4* p3 = (const float4*)(g_part + (size_t)(base + 3) * (MSLOTS * EDIM));
    float4 a = p0[i], b = p1[i], c = p2[i], d = p3[i];
    float4 o;
    o.x = to_tf32((a.x + b.x) + (c.x + d.x));
    o.y = to_tf32((a.y + b.y) + (c.y + d.y));
    o.z = to_tf32((a.z + b.z) + (c.z + d.z));
    o.w = to_tf32((a.w + b.w) + (c.w + d.w));
    float4* dst = (base == 0) ? (float4*)g_P : (float4*)g_Rt;
    dst[i] = o;
}

__global__ void s0_kernel(const float* __restrict__ Mb, const float* __restrict__ bq)
{
    int m = blockIdx.x;
    int lane = threadIdx.x;
    float s = 0.f;
    #pragma unroll
    for (int c = 0; c < 8; c++) {
        int e = lane * 4 + c * 128;
        float4 mv = *(const float4*)(Mb + (size_t)m * EDIM + e);
        float4 bv = *(const float4*)(bq + e);
        s += mv.x * bv.x + mv.y * bv.y + mv.z * bv.z + mv.w * bv.w;
    }
    #pragma unroll
    for (int o = 16; o; o >>= 1) s += __shfl_xor_sync(0xffffffffu, s, o);
    if (lane == 0) g_s0[m] = s;
}

// ---------------------------------------------------------------------------
// scores + softmax: CTA = 64 rows x 256 slots, K=1024, mma.sync tf32.
// 256 threads = 8 warps in 2x4 grid, warp tile 32x64. 2 CTAs/SM.
// (exact round-10 structure — best measured variant; mainloop FROZEN)
// ---------------------------------------------------------------------------
#define S_AST (64 * LDK * 4)          // 5120
#define S_BST (256 * LDK * 4)         // 20480
#define S_ST  (S_AST + S_BST)         // 25600
#define S_OFF_S0  0
#define S_OFF_RED 1024
#define S_OFF_STG 2048
#define S_SMEM (S_OFF_STG + 4 * S_ST) // 104448

__global__ __launch_bounds__(256, 2) void scores_tc(const float* __restrict__ x)
{
    extern __shared__ char smem[];
    const uint32_t sb = smem_u32(smem);
    const int tid = threadIdx.x;
    const int lane = tid & 31, wid = tid >> 5;
    const int wm = wid >> 2, wn = wid & 3;       // warp grid 2x4
    const int g = lane >> 2, q = lane & 3;
    const int row0 = blockIdx.x * 64;

    if (tid < 64) ((float4*)(smem + S_OFF_S0))[tid] = ((const float4*)g_s0)[tid];

    auto load_stage = [&](int buf, int kb) {
        uint32_t ab = sb + S_OFF_STG + buf * S_ST;
        uint32_t bb = ab + S_AST;
        {   // A: x[row0..row0+63, kb..kb+15]
            int r = tid >> 2, t = tid & 3;
            cp16(ab + (r * LDK + t * 4) * 4, x + (size_t)(row0 + r) * EDIM + kb + t * 4);
        }
        #pragma unroll
        for (int i = 0; i < 4; i++) {   // B: g_P[0..255, kb..kb+15]
            int idx = tid + i * 256;
            int r = idx >> 2, t = idx & 3;
            cp16(bb + (r * LDK + t * 4) * 4, g_P + (size_t)r * EDIM + kb + t * 4);
        }
    };

    float acc[2][8][4] = {};
    #pragma unroll
    for (int p = 0; p < 3; p++) { load_stage(p, p * 16); CP_COMMIT(); }

    for (int s = 0; s < 64; s++) {
        CP_WAIT(2);
        __syncthreads();
        if (s + 3 < 64) load_stage((s + 3) & 3, (s + 3) * 16);
        CP_COMMIT();

        uint32_t aB = sb + S_OFF_STG + (s & 3) * S_ST;
        uint32_t bB = aB + S_AST;
        #pragma unroll
        for (int k8 = 0; k8 < 16; k8 += 8) {
            uint32_t af[2][4], bf[8][2];
            #pragma unroll
            for (int mb = 0; mb < 2; mb++) {
                int row = wm * 32 + mb * 16 + ((lane >> 3) & 1) * 8 + (lane & 7);
                int kof = k8 + ((lane >> 4) << 2);
                LDSM4(af[mb][0], af[mb][1], af[mb][2], af[mb][3],
                      aB + (row * LDK + kof) * 4);
            }
            #pragma unroll
            for (int nb2 = 0; nb2 < 4; nb2++) {
                int n = wn * 64 + nb2 * 16 + ((lane >> 4) & 1) * 8 + (lane & 7);
                int kof = k8 + ((lane >> 3) & 1) * 4;
                LDSM4(bf[nb2*2][0], bf[nb2*2][1], bf[nb2*2+1][0], bf[nb2*2+1][1],
                      bB + (n * LDK + kof) * 4);
            }
            // x is raw fp32 -> round A frags to tf32 (B already rounded)
            #pragma unroll
            for (int mb = 0; mb < 2; mb++)
                #pragma unroll
                for (int i = 0; i < 4; i++) cvt_tf32_r(af[mb][i]);
            #pragma unroll
            for (int mb = 0; mb < 2; mb++)
                #pragma unroll
                for (int nb = 0; nb < 8; nb++)
                    MMA_TF32(acc[mb][nb], af[mb], bf[nb]);
        }
    }

    // ---- softmax epilogue ----
    const float* s0s = (const float*)(smem + S_OFF_S0);
    float* red = (float*)(smem + S_OFF_RED);   // [64 rows][4 col-warps]

    #pragma unroll
    for (int nb = 0; nb < 8; nb++) {
        float2 sp = *(const float2*)(s0s + wn * 64 + nb * 8 + q * 2);
        #pragma unroll
        for (int mb = 0; mb < 2; mb++) {
            acc[mb][nb][0] += sp.x; acc[mb][nb][1] += sp.y;
            acc[mb][nb][2] += sp.x; acc[mb][nb][3] += sp.y;
        }
    }
    float mx[2][2];
    #pragma unroll
    for (int mb = 0; mb < 2; mb++)
        #pragma unroll
        for (int r = 0; r < 2; r++) {
            float m = -1e30f;
            #pragma unroll
            for (int nb = 0; nb < 8; nb++)
                m = fmaxf(m, fmaxf(acc[mb][nb][r*2], acc[mb][nb][r*2+1]));
            m = fmaxf(m, __shfl_xor_sync(0xffffffffu, m, 1));
            m = fmaxf(m, __shfl_xor_sync(0xffffffffu, m, 2));
            if (q == 0) red[(wm * 32 + mb * 16 + g + r * 8) * 4 + wn] = m;
        }
    __syncthreads();
    #pragma unroll
    for (int mb = 0; mb < 2; mb++)
        #pragma unroll
        for (int r = 0; r < 2; r++) {
            int row = wm * 32 + mb * 16 + g + r * 8;
            float4 rv = *(const float4*)(red + row * 4);
            mx[mb][r] = fmaxf(fmaxf(rv.x, rv.y), fmaxf(rv.z, rv.w));
        }
    __syncthreads();
    #pragma unroll
    for (int mb = 0; mb < 2; mb++)
        #pragma unroll
        for (int r = 0; r < 2; r++) {
            float s = 0.f;
            #pragma unroll
            for (int nb = 0; nb < 8; nb++) {
                float e0 = __expf(acc[mb][nb][r*2]   - mx[mb][r]);
                float e1 = __expf(acc[mb][nb][r*2+1] - mx[mb][r]);
                acc[mb][nb][r*2] = e0; acc[mb][nb][r*2+1] = e1;
                s += e0 + e1;
            }
            s += __shfl_xor_sync(0xffffffffu, s, 1);
            s += __shfl_xor_sync(0xffffffffu, s, 2);
            if (q == 0) red[(wm * 32 + mb * 16 + g + r * 8) * 4 + wn] = s;
        }
    __syncthreads();
    #pragma unroll
    for (int mb = 0; mb < 2; mb++)
        #pragma unroll
        for (int r = 0; r < 2; r++) {
            int row = wm * 32 + mb * 16 + g + r * 8;
            float4 rv = *(const float4*)(red + row * 4);
            float inv = 1.f / (rv.x + rv.y + rv.z + rv.w);
            size_t grow = (size_t)(row0 + row);
            #pragma unroll
            for (int nb = 0; nb < 8; nb++) {
                float2 o;
                o.x = to_tf32(acc[mb][nb][r*2]   * inv);
                o.y = to_tf32(acc[mb][nb][r*2+1] * inv);
                *(float2*)(g_w + grow * MSLOTS + wn * 64 + nb * 8 + q * 2) = o;
            }
        }
}

// ---------------------------------------------------------------------------
// out = w @ Rt^T + bo + x: CTA = 64 rows x 128 cols, K=256, mma.sync tf32.
// 256 threads = 8 warps in 2x4 grid, warp tile 32x32. 3 CTAs/SM (acc=32 regs).
// x residual tile (64x128) prefetched into freed ring buffers.
// ---------------------------------------------------------------------------
#define O_AST (64 * LDK * 4)          // 5120
#define O_BST (128 * LDK * 4)         // 10240
#define O_ST  (O_AST + O_BST)         // 15360
#define O_SMEM (4 * O_ST)             // 61440; x tile 64*LDX*4=33792 fits

__global__ __launch_bounds__(256, 3) void out_tc(
    const float* __restrict__ x, const float* __restrict__ bo,
    float* __restrict__ out)
{
    extern __shared__ char smem[];
    const uint32_t sb = smem_u32(smem);
    const int tid = threadIdx.x;
    const int lane = tid & 31, wid = tid >> 5;
    const int wm = wid >> 2, wn = wid & 3;       // warp grid 2x4
    const int g = lane >> 2, q = lane & 3;
    const int row0 = blockIdx.y * 64;
    const int col0 = blockIdx.x * 128;

    auto load_stage = [&](int buf, int kb) {
        uint32_t ab = sb + buf * O_ST;
        uint32_t bb = ab + O_AST;
        {   // A: g_w[row0..+63, kb..kb+15] -- 256 cp16
            int r = tid >> 2, t = tid & 3;
            cp16(ab + (r * LDK + t * 4) * 4, g_w + (size_t)(row0 + r) * MSLOTS + kb + t * 4);
        }
        #pragma unroll
        for (int i = 0; i < 2; i++) {   // B: g_Rt[col0..+127, kb..kb+15]
            int idx = tid + i * 256;
            int r = idx >> 2, t = idx & 3;
            cp16(bb + (r * LDK + t * 4) * 4, g_Rt + (size_t)(col0 + r) * MSLOTS + kb + t * 4);
        }
    };

    // x chunk c: rows 16c..16c+15 of the 64x128 tile into LDX-stride smem.
    // Chunk c ends at (16c+16)*LDX*4 = (c+1)*8448 <= (c+1)*O_ST -> chunk c
    // only touches ring buffers 0..c, free when issued (c=0,1,2 at s=13,14,15).
    auto load_x_chunk = [&](int c) {
        #pragma unroll
        for (int i = 0; i < 2; i++) {   // 16 rows x 32 cp16
            int idx = tid + i * 256;
            int r = idx >> 5, t = idx & 31;
            cp16(sb + ((c * 16 + r) * LDX + t * 4) * 4,
                 x + (size_t)(row0 + c * 16 + r) * EDIM + col0 + t * 4);
        }
    };

    float acc[2][4][4] = {};
    #pragma unroll
    for (int p = 0; p < 3; p++) { load_stage(p, p * 16); CP_COMMIT(); }

    for (int s = 0; s < 16; s++) {
        CP_WAIT(2);
        __syncthreads();
        if (s + 3 < 16) load_stage((s + 3) & 3, (s + 3) * 16);
        else            load_x_chunk(s - 13);   // s=13,14,15 -> chunks 0,1,2
        CP_COMMIT();

        uint32_t aB = sb + (s & 3) * O_ST;
        uint32_t bB = aB + O_AST;
        #pragma unroll
        for (int k8 = 0; k8 < 16; k8 += 8) {
            uint32_t af[2][4], bf[4][2];
            #pragma unroll
            for (int mb = 0; mb < 2; mb++) {
                int row = wm * 32 + mb * 16 + ((lane >> 3) & 1) * 8 + (lane & 7);
                int kof = k8 + ((lane >> 4) << 2);
                LDSM4(af[mb][0], af[mb][1], af[mb][2], af[mb][3],
                      aB + (row * LDK + kof) * 4);
            }
            #pragma unroll
            for (int nb2 = 0; nb2 < 2; nb2++) {
                int n = wn * 32 + nb2 * 16 + ((lane >> 4) & 1) * 8 + (lane & 7);
                int kof = k8 + ((lane >> 3) & 1) * 4;
                LDSM4(bf[nb2*2][0], bf[nb2*2][1], bf[nb2*2+1][0], bf[nb2*2+1][1],
                      bB + (n * LDK + kof) * 4);
            }
            // both operands pre-rounded to tf32 -> no cvt needed
            #pragma unroll
            for (int mb = 0; mb < 2; mb++)
                #pragma unroll
                for (int nb = 0; nb < 4; nb++)
                    MMA_TF32(acc[mb][nb], af[mb], bf[nb]);
        }
    }

    // buf3 free only after ALL warps finished stage 15's reads
    __syncthreads();
    load_x_chunk(3);
    CP_COMMIT();
    CP_WAIT(0);
    __syncthreads();

    // ---- epilogue: + bo + x (x from smem) ----
    const float* xs = (const float*)smem;
    #pragma unroll
    for (int mb = 0; mb < 2; mb++)
        #pragma unroll
        for (int r = 0; r < 2; r++) {
            int lrow = wm * 32 + mb * 16 + g + r * 8;
            size_t row = (size_t)(row0 + lrow);
            #pragma unroll
            for (int nb = 0; nb < 4; nb++) {
                int lcol = wn * 32 + nb * 8 + q * 2;
                float2 xv = *(const float2*)(xs + lrow * LDX + lcol);
                float2 bv = *(const float2*)(bo + col0 + lcol);
                float2 o;
                o.x = acc[mb][nb][r*2]   + bv.x + xv.x;
                o.y = acc[mb][nb][r*2+1] + bv.y + xv.y;
                *(float2*)(out + row * EDIM + col0 + lcol) = o;
            }
        }
}

// ---------------------------------------------------------------------------
// Launch
// ---------------------------------------------------------------------------
extern "C" void kernel_launch(void* const* d_in, const int* in_sizes, int n_in,
                              void* d_out, int out_size)
{
    (void)in_sizes; (void)n_in; (void)out_size;
    const float* x  = (const float*)d_in[0];
    const float* Mb = (const float*)d_in[1];
    const float* Wq = (const float*)d_in[2];
    const float* bq = (const float*)d_in[3];
    const float* Wo = (const float*)d_in[4];
    const float* bo = (const float*)d_in[5];
    float* out = (float*)d_out;

    cudaFuncSetAttribute(scores_tc, cudaFuncAttributeMaxDynamicSharedMemorySize, S_SMEM);
    cudaFuncSetAttribute(out_tc,    cudaFuncAttributeMaxDynamicSharedMemorySize, O_SMEM);

    precompute_part<<<dim3(EDIM / 64, MSLOTS / 64, 8), 256>>>(Mb, Wq, Wo);
    reduce_pre<<<512, 256>>>();
    s0_kernel<<<MSLOTS, 32>>>(Mb, bq);
    scores_tc<<<NROWS / 64, 256, S_SMEM>>>(x);
    out_tc<<<dim3(EDIM / 128, NROWS / 64), 256, O_SMEM>>>(x, bo, out);
}

// round 13
// speedup vs baseline: 1.0525x; 1.0525x over previous
#include <cuda_runtime.h>
#include <cstdint>

#define EDIM   1024
#define MSLOTS 256
#define NROWS  32768

// Scratch (no allocations -> __device__ globals). P/Rt pre-rounded to tf32.
__device__ float g_P [MSLOTS * EDIM];              // P  = M @ Wq       [slot, e]
__device__ float g_Rt[EDIM * MSLOTS];              // Rt = (M @ Wo^T)^T [e, slot]
__device__ float g_s0[MSLOTS];                     // s0 = M @ bq  (full fp32)
__device__ float g_w [(size_t)NROWS * MSLOTS];     // softmax weights   [row, slot]
__device__ float g_part[16 * MSLOTS * EDIM];       // K-split partials: [mode*8+ks]

// ---------------------------------------------------------------------------
// Helpers
// ---------------------------------------------------------------------------
__device__ __forceinline__ uint32_t smem_u32(const void* p) {
    uint32_t a;
    asm("{ .reg .u64 t; cvta.to.shared.u64 t, %1; cvt.u32.u64 %0, t; }" : "=r"(a) : "l"(p));
    return a;
}
__device__ __forceinline__ void cp16(uint32_t dst, const void* src) {
    asm volatile("cp.async.cg.shared.global [%0], [%1], 16;" :: "r"(dst), "l"(src));
}
#define CP_COMMIT() asm volatile("cp.async.commit_group;" ::: "memory")
#define CP_WAIT(n)  asm volatile("cp.async.wait_group %0;" :: "n"(n) : "memory")

#define LDSM4(r0, r1, r2, r3, addr) \
    asm volatile("ldmatrix.sync.aligned.m8n8.x4.shared.b16 {%0,%1,%2,%3}, [%4];" \
        : "=r"(r0), "=r"(r1), "=r"(r2), "=r"(r3) : "r"(addr))

#define MMA_TF32(c, a, b) \
    asm volatile("mma.sync.aligned.m16n8k8.row.col.f32.tf32.tf32.f32 " \
        "{%0,%1,%2,%3}, {%4,%5,%6,%7}, {%8,%9}, {%0,%1,%2,%3};" \
        : "+f"((c)[0]), "+f"((c)[1]), "+f"((c)[2]), "+f"((c)[3]) \
        : "r"((a)[0]), "r"((a)[1]), "r"((a)[2]), "r"((a)[3]), "r"((b)[0]), "r"((b)[1]))

__device__ __forceinline__ float to_tf32(float v) {
    uint32_t u;
    asm("cvt.rna.tf32.f32 %0, %1;" : "=r"(u) : "f"(v));
    return __uint_as_float(u);
}
__device__ __forceinline__ void cvt_tf32_r(uint32_t& u) {
    asm("cvt.rna.tf32.f32 %0, %0;" : "+r"(u));
}

// Padded K stride (floats): 16 + 4 -> 80B rows, conflict-free ldmatrix
#define LDK 20
// x-residual smem row stride (floats): 128 + 4 pad (16B-aligned rows)
#define LDX 132

// ---------------------------------------------------------------------------
// Precompute partials with K-split x8: z = mode*8 + ks, K window = ks*128..+128
// ---------------------------------------------------------------------------
__global__ __launch_bounds__(256) void precompute_part(
    const float* __restrict__ Mb, const float* __restrict__ Wq,
    const float* __restrict__ Wo)
{
    constexpr int BM = 64, BN = 64, BK = 32;
    __shared__ float As[BK][BM];
    __shared__ float Bs[BK][BN];
    const int mode = blockIdx.z >> 3;
    const int ks   = blockIdx.z & 7;
    const int m0 = blockIdx.y * BM;
    const int n0 = blockIdx.x * BN;
    const int tid = threadIdx.x;
    const int tm = tid >> 4, tn = tid & 15;
    const int kbeg = ks * 128;
    float acc[4][4] = {};

    for (int kb = kbeg; kb < kbeg + 128; kb += BK) {
        {
            int r = tid >> 2, k0 = (tid & 3) * 8;
            float4 v0 = *(const float4*)(Mb + (m0 + r) * EDIM + kb + k0);
            float4 v1 = *(const float4*)(Mb + (m0 + r) * EDIM + kb + k0 + 4);
            As[k0+0][r] = v0.x; As[k0+1][r] = v0.y; As[k0+2][r] = v0.z; As[k0+3][r] = v0.w;
            As[k0+4][r] = v1.x; As[k0+5][r] = v1.y; As[k0+6][r] = v1.z; As[k0+7][r] = v1.w;
        }
        if (mode == 0) {
            int k = tid >> 3, nq = (tid & 7) * 8;
            float4 v0 = *(const float4*)(Wq + (size_t)(kb + k) * EDIM + n0 + nq);
            float4 v1 = *(const float4*)(Wq + (size_t)(kb + k) * EDIM + n0 + nq + 4);
            *(float4*)&Bs[k][nq]     = v0;
            *(float4*)&Bs[k][nq + 4] = v1;
        } else {
            int n = tid >> 2, k0 = (tid & 3) * 8;
            float4 v0 = *(const float4*)(Wo + (size_t)(n0 + n) * EDIM + kb + k0);
            float4 v1 = *(const float4*)(Wo + (size_t)(n0 + n) * EDIM + kb + k0 + 4);
            Bs[k0+0][n] = v0.x; Bs[k0+1][n] = v0.y; Bs[k0+2][n] = v0.z; Bs[k0+3][n] = v0.w;
            Bs[k0+4][n] = v1.x; Bs[k0+5][n] = v1.y; Bs[k0+6][n] = v1.z; Bs[k0+7][n] = v1.w;
        }
        __syncthreads();
        #pragma unroll
        for (int k = 0; k < BK; k++) {
            float a[4], b[4];
            *(float4*)a = *(const float4*)&As[k][tm * 4];
            *(float4*)b = *(const float4*)&Bs[k][tn * 4];
            #pragma unroll
            for (int i = 0; i < 4; i++)
                #pragma unroll
                for (int j = 0; j < 4; j++)
                    acc[i][j] = fmaf(a[i], b[j], acc[i][j]);
        }
        __syncthreads();
    }
    if (mode == 0) {
        float* dst = g_part + (size_t)ks * (MSLOTS * EDIM);
        #pragma unroll
        for (int i = 0; i < 4; i++) {
            int m = m0 + tm * 4 + i;
            *(float4*)(dst + (size_t)m * EDIM + n0 + tn * 4) =
                make_float4(acc[i][0], acc[i][1], acc[i][2], acc[i][3]);
        }
    } else {
        float* dst = g_part + (size_t)(8 + ks) * (MSLOTS * EDIM);
        #pragma unroll
        for (int i = 0; i < 4; i++)
            #pragma unroll
            for (int j = 0; j < 4; j++)
                dst[(size_t)(n0 + tn * 4 + j) * MSLOTS + (m0 + tm * 4 + i)] = acc[i][j];
    }
}

// Sum 8 K-split partials, round to tf32. t < 65536 -> P float4 t; else Rt.
__global__ __launch_bounds__(256) void reduce_pre()
{
    int t = blockIdx.x * 256 + threadIdx.x;      // 0..131071 (float4 index)
    const int NF4 = MSLOTS * EDIM / 4;           // 65536
    int base = (t < NF4) ? 0 : 8;
    int i = (t < NF4) ? t : t - NF4;
    float4 s0v = make_float4(0.f, 0.f, 0.f, 0.f);
    float4 s1v = make_float4(0.f, 0.f, 0.f, 0.f);
    #pragma unroll
    for (int p = 0; p < 8; p += 2) {
        float4 a = ((const float4*)(g_part + (size_t)(base + p)     * (MSLOTS * EDIM)))[i];
        float4 b = ((const float4*)(g_part + (size_t)(base + p + 1) * (MSLOTS * EDIM)))[i];
        s0v.x += a.x; s0v.y += a.y; s0v.z += a.z; s0v.w += a.w;
        s1v.x += b.x; s1v.y += b.y; s1v.z += b.z; s1v.w += b.w;
    }
    float4 o;
    o.x = to_tf32(s0v.x + s1v.x);
    o.y = to_tf32(s0v.y + s1v.y);
    o.z = to_tf32(s0v.z + s1v.z);
    o.w = to_tf32(s0v.w + s1v.w);
    float4* dst = (base == 0) ? (float4*)g_P : (float4*)g_Rt;
    dst[i] = o;
}

__global__ void s0_kernel(const float* __restrict__ Mb, const float* __restrict__ bq)
{
    int m = blockIdx.x;
    int lane = threadIdx.x;
    float s = 0.f;
    #pragma unroll
    for (int c = 0; c < 8; c++) {
        int e = lane * 4 + c * 128;
        float4 mv = *(const float4*)(Mb + (size_t)m * EDIM + e);
        float4 bv = *(const float4*)(bq + e);
        s += mv.x * bv.x + mv.y * bv.y + mv.z * bv.z + mv.w * bv.w;
    }
    #pragma unroll
    for (int o = 16; o; o >>= 1) s += __shfl_xor_sync(0xffffffffu, s, o);
    if (lane == 0) g_s0[m] = s;
}

// ---------------------------------------------------------------------------
// scores + softmax: CTA = 64 rows x 256 slots, K=1024, mma.sync tf32.
// 256 threads = 8 warps in 2x4 grid, warp tile 32x64. 2 CTAs/SM.
// (round-10 structure — FROZEN)
// ---------------------------------------------------------------------------
#define S_AST (64 * LDK * 4)          // 5120
#define S_BST (256 * LDK * 4)         // 20480
#define S_ST  (S_AST + S_BST)         // 25600
#define S_OFF_S0  0
#define S_OFF_RED 1024
#define S_OFF_STG 2048
#define S_SMEM (S_OFF_STG + 4 * S_ST) // 104448

__global__ __launch_bounds__(256, 2) void scores_tc(const float* __restrict__ x)
{
    extern __shared__ char smem[];
    const uint32_t sb = smem_u32(smem);
    const int tid = threadIdx.x;
    const int lane = tid & 31, wid = tid >> 5;
    const int wm = wid >> 2, wn = wid & 3;       // warp grid 2x4
    const int g = lane >> 2, q = lane & 3;
    const int row0 = blockIdx.x * 64;

    if (tid < 64) ((float4*)(smem + S_OFF_S0))[tid] = ((const float4*)g_s0)[tid];

    auto load_stage = [&](int buf, int kb) {
        uint32_t ab = sb + S_OFF_STG + buf * S_ST;
        uint32_t bb = ab + S_AST;
        {   // A: x[row0..row0+63, kb..kb+15]
            int r = tid >> 2, t = tid & 3;
            cp16(ab + (r * LDK + t * 4) * 4, x + (size_t)(row0 + r) * EDIM + kb + t * 4);
        }
        #pragma unroll
        for (int i = 0; i < 4; i++) {   // B: g_P[0..255, kb..kb+15]
            int idx = tid + i * 256;
            int r = idx >> 2, t = idx & 3;
            cp16(bb + (r * LDK + t * 4) * 4, g_P + (size_t)r * EDIM + kb + t * 4);
        }
    };

    float acc[2][8][4] = {};
    #pragma unroll
    for (int p = 0; p < 3; p++) { load_stage(p, p * 16); CP_COMMIT(); }

    for (int s = 0; s < 64; s++) {
        CP_WAIT(2);
        __syncthreads();
        if (s + 3 < 64) load_stage((s + 3) & 3, (s + 3) * 16);
        CP_COMMIT();

        uint32_t aB = sb + S_OFF_STG + (s & 3) * S_ST;
        uint32_t bB = aB + S_AST;
        #pragma unroll
        for (int k8 = 0; k8 < 16; k8 += 8) {
            uint32_t af[2][4], bf[8][2];
            #pragma unroll
            for (int mb = 0; mb < 2; mb++) {
                int row = wm * 32 + mb * 16 + ((lane >> 3) & 1) * 8 + (lane & 7);
                int kof = k8 + ((lane >> 4) << 2);
                LDSM4(af[mb][0], af[mb][1], af[mb][2], af[mb][3],
                      aB + (row * LDK + kof) * 4);
            }
            #pragma unroll
            for (int nb2 = 0; nb2 < 4; nb2++) {
                int n = wn * 64 + nb2 * 16 + ((lane >> 4) & 1) * 8 + (lane & 7);
                int kof = k8 + ((lane >> 3) & 1) * 4;
                LDSM4(bf[nb2*2][0], bf[nb2*2][1], bf[nb2*2+1][0], bf[nb2*2+1][1],
                      bB + (n * LDK + kof) * 4);
            }
            // x is raw fp32 -> round A frags to tf32 (B already rounded)
            #pragma unroll
            for (int mb = 0; mb < 2; mb++)
                #pragma unroll
                for (int i = 0; i < 4; i++) cvt_tf32_r(af[mb][i]);
            #pragma unroll
            for (int mb = 0; mb < 2; mb++)
                #pragma unroll
                for (int nb = 0; nb < 8; nb++)
                    MMA_TF32(acc[mb][nb], af[mb], bf[nb]);
        }
    }

    // ---- softmax epilogue ----
    const float* s0s = (const float*)(smem + S_OFF_S0);
    float* red = (float*)(smem + S_OFF_RED);   // [64 rows][4 col-warps]

    #pragma unroll
    for (int nb = 0; nb < 8; nb++) {
        float2 sp = *(const float2*)(s0s + wn * 64 + nb * 8 + q * 2);
        #pragma unroll
        for (int mb = 0; mb < 2; mb++) {
            acc[mb][nb][0] += sp.x; acc[mb][nb][1] += sp.y;
            acc[mb][nb][2] += sp.x; acc[mb][nb][3] += sp.y;
        }
    }
    float mx[2][2];
    #pragma unroll
    for (int mb = 0; mb < 2; mb++)
        #pragma unroll
        for (int r = 0; r < 2; r++) {
            float m = -1e30f;
            #pragma unroll
            for (int nb = 0; nb < 8; nb++)
                m = fmaxf(m, fmaxf(acc[mb][nb][r*2], acc[mb][nb][r*2+1]));
            m = fmaxf(m, __shfl_xor_sync(0xffffffffu, m, 1));
            m = fmaxf(m, __shfl_xor_sync(0xffffffffu, m, 2));
            if (q == 0) red[(wm * 32 + mb * 16 + g + r * 8) * 4 + wn] = m;
        }
    __syncthreads();
    #pragma unroll
    for (int mb = 0; mb < 2; mb++)
        #pragma unroll
        for (int r = 0; r < 2; r++) {
            int row = wm * 32 + mb * 16 + g + r * 8;
            float4 rv = *(const float4*)(red + row * 4);
            mx[mb][r] = fmaxf(fmaxf(rv.x, rv.y), fmaxf(rv.z, rv.w));
        }
    __syncthreads();
    #pragma unroll
    for (int mb = 0; mb < 2; mb++)
        #pragma unroll
        for (int r = 0; r < 2; r++) {
            float s = 0.f;
            #pragma unroll
            for (int nb = 0; nb < 8; nb++) {
                float e0 = __expf(acc[mb][nb][r*2]   - mx[mb][r]);
                float e1 = __expf(acc[mb][nb][r*2+1] - mx[mb][r]);
                acc[mb][nb][r*2] = e0; acc[mb][nb][r*2+1] = e1;
                s += e0 + e1;
            }
            s += __shfl_xor_sync(0xffffffffu, s, 1);
            s += __shfl_xor_sync(0xffffffffu, s, 2);
            if (q == 0) red[(wm * 32 + mb * 16 + g + r * 8) * 4 + wn] = s;
        }
    __syncthreads();
    #pragma unroll
    for (int mb = 0; mb < 2; mb++)
        #pragma unroll
        for (int r = 0; r < 2; r++) {
            int row = wm * 32 + mb * 16 + g + r * 8;
            float4 rv = *(const float4*)(red + row * 4);
            float inv = 1.f / (rv.x + rv.y + rv.z + rv.w);
            size_t grow = (size_t)(row0 + row);
            #pragma unroll
            for (int nb = 0; nb < 8; nb++) {
                float2 o;
                o.x = to_tf32(acc[mb][nb][r*2]   * inv);
                o.y = to_tf32(acc[mb][nb][r*2+1] * inv);
                *(float2*)(g_w + grow * MSLOTS + wn * 64 + nb * 8 + q * 2) = o;
            }
        }
}

// ---------------------------------------------------------------------------
// out = w @ Rt^T + bo + x: CTA = 128 rows x 128 cols, K=256, mma.sync tf32.
// 256 threads = 8 warps in 2x4 grid, warp tile 64x32. 2 CTAs/SM.
// (round-10 structure — FROZEN; x tile prefetched into freed ring buffers)
// ---------------------------------------------------------------------------
#define O_AST (128 * LDK * 4)         // 10240
#define O_BST (128 * LDK * 4)         // 10240
#define O_ST  (O_AST + O_BST)         // 20480
#define O_SMEM (4 * O_ST)             // 81920; x tile 128*LDX*4=67584 fits

__global__ __launch_bounds__(256, 2) void out_tc(
    const float* __restrict__ x, const float* __restrict__ bo,
    float* __restrict__ out)
{
    extern __shared__ char smem[];
    const uint32_t sb = smem_u32(smem);
    const int tid = threadIdx.x;
    const int lane = tid & 31, wid = tid >> 5;
    const int wm = wid >> 2, wn = wid & 3;       // warp grid 2x4
    const int g = lane >> 2, q = lane & 3;
    const int row0 = blockIdx.y * 128;
    const int col0 = blockIdx.x * 128;

    auto load_stage = [&](int buf, int kb) {
        uint32_t ab = sb + buf * O_ST;
        uint32_t bb = ab + O_AST;
        #pragma unroll
        for (int i = 0; i < 2; i++) {   // A: g_w[row0..+127, kb..kb+15]
            int idx = tid + i * 256;
            int r = idx >> 2, t = idx & 3;
            cp16(ab + (r * LDK + t * 4) * 4, g_w + (size_t)(row0 + r) * MSLOTS + kb + t * 4);
        }
        #pragma unroll
        for (int i = 0; i < 2; i++) {   // B: g_Rt[col0..+127, kb..kb+15]
            int idx = tid + i * 256;
            int r = idx >> 2, t = idx & 3;
            cp16(bb + (r * LDK + t * 4) * 4, g_Rt + (size_t)(col0 + r) * MSLOTS + kb + t * 4);
        }
    };

    // x chunk c: rows 32c..32c+31 of the 128x128 tile into LDX-stride smem.
    // Chunk c's bytes end at (32c+32)*LDX*4 <= (c+1)*O_ST -> each chunk only
    // touches ring buffers 0..c, which are free when it's issued.
    auto load_x_chunk = [&](int c) {
        #pragma unroll
        for (int i = 0; i < 4; i++) {   // 32 rows x 32 cp16
            int idx = tid + i * 256;
            int r = idx >> 5, t = idx & 31;
            cp16(sb + ((c * 32 + r) * LDX + t * 4) * 4,
                 x + (size_t)(row0 + c * 32 + r) * EDIM + col0 + t * 4);
        }
    };

    float acc[4][4][4] = {};
    #pragma unroll
    for (int p = 0; p < 3; p++) { load_stage(p, p * 16); CP_COMMIT(); }

    for (int s = 0; s < 16; s++) {
        CP_WAIT(2);
        __syncthreads();
        if (s + 3 < 16) load_stage((s + 3) & 3, (s + 3) * 16);
        else            load_x_chunk(s - 13);   // s=13,14,15 -> chunks 0,1,2
        CP_COMMIT();

        uint32_t aB = sb + (s & 3) * O_ST;
        uint32_t bB = aB + O_AST;
        #pragma unroll
        for (int k8 = 0; k8 < 16; k8 += 8) {
            uint32_t af[4][4], bf[4][2];
            #pragma unroll
            for (int mb = 0; mb < 4; mb++) {
                int row = wm * 64 + mb * 16 + ((lane >> 3) & 1) * 8 + (lane & 7);
                int kof = k8 + ((lane >> 4) << 2);
                LDSM4(af[mb][0], af[mb][1], af[mb][2], af[mb][3],
                      aB + (row * LDK + kof) * 4);
            }
            #pragma unroll
            for (int nb2 = 0; nb2 < 2; nb2++) {
                int n = wn * 32 + nb2 * 16 + ((lane >> 4) & 1) * 8 + (lane & 7);
                int kof = k8 + ((lane >> 3) & 1) * 4;
                LDSM4(bf[nb2*2][0], bf[nb2*2][1], bf[nb2*2+1][0], bf[nb2*2+1][1],
                      bB + (n * LDK + kof) * 4);
            }
            // both operands pre-rounded to tf32 -> no cvt needed
            #pragma unroll
            for (int mb = 0; mb < 4; mb++)
                #pragma unroll
                for (int nb = 0; nb < 4; nb++)
                    MMA_TF32(acc[mb][nb], af[mb], bf[nb]);
        }
    }

    // buf3 free only after ALL warps finished stage 15's reads
    __syncthreads();
    load_x_chunk(3);
    CP_COMMIT();
    CP_WAIT(0);
    __syncthreads();

    // ---- epilogue: + bo + x (x from smem) ----
    const float* xs = (const float*)smem;
    #pragma unroll
    for (int mb = 0; mb < 4; mb++)
        #pragma unroll
        for (int r = 0; r < 2; r++) {
            int lrow = wm * 64 + mb * 16 + g + r * 8;
            size_t row = (size_t)(row0 + lrow);
            #pragma unroll
            for (int nb = 0; nb < 4; nb++) {
                int lcol = wn * 32 + nb * 8 + q * 2;
                float2 xv = *(const float2*)(xs + lrow * LDX + lcol);
                float2 bv = *(const float2*)(bo + col0 + lcol);
                float2 o;
                o.x = acc[mb][nb][r*2]   + bv.x + xv.x;
                o.y = acc[mb][nb][r*2+1] + bv.y + xv.y;
                *(float2*)(out + row * EDIM + col0 + lcol) = o;
            }
        }
}

// ---------------------------------------------------------------------------
// Launch
// ---------------------------------------------------------------------------
extern "C" void kernel_launch(void* const* d_in, const int* in_sizes, int n_in,
                              void* d_out, int out_size)
{
    (void)in_sizes; (void)n_in; (void)out_size;
    const float* x  = (const float*)d_in[0];
    const float* Mb = (const float*)d_in[1];
    const float* Wq = (const float*)d_in[2];
    const float* bq = (const float*)d_in[3];
    const float* Wo = (const float*)d_in[4];
    const float* bo = (const float*)d_in[5];
    float* out = (float*)d_out;

    cudaFuncSetAttribute(scores_tc, cudaFuncAttributeMaxDynamicSharedMemorySize, S_SMEM);
    cudaFuncSetAttribute(out_tc,    cudaFuncAttributeMaxDynamicSharedMemorySize, O_SMEM);

    precompute_part<<<dim3(EDIM / 64, MSLOTS / 64, 16), 256>>>(Mb, Wq, Wo);
    reduce_pre<<<512, 256>>>();
    s0_kernel<<<MSLOTS, 32>>>(Mb, bq);
    scores_tc<<<NROWS / 64, 256, S_SMEM>>>(x);
    out_tc<<<dim3(EDIM / 128, NROWS / 128), 256, O_SMEM>>>(x, bo, out);
}

// round 14
// speedup vs baseline: 1.0570x; 1.0043x over previous
#include <cuda_runtime.h>
#include <cstdint>

#define EDIM   1024
#define MSLOTS 256
#define NROWS  32768

// Scratch (no allocations -> __device__ globals). P/Rt pre-rounded to tf32.
__device__ float g_P [MSLOTS * EDIM];              // P  = M @ Wq       [slot, e]
__device__ float g_Rt[EDIM * MSLOTS];              // Rt = (M @ Wo^T)^T [e, slot]
__device__ float g_s0[MSLOTS];                     // s0 = M @ bq  (full fp32)
__device__ float g_w [(size_t)NROWS * MSLOTS];     // softmax weights   [row, slot]
__device__ float g_part[16 * MSLOTS * EDIM];       // K-split partials: [mode*8+ks]

// ---------------------------------------------------------------------------
// Helpers
// ---------------------------------------------------------------------------
__device__ __forceinline__ uint32_t smem_u32(const void* p) {
    uint32_t a;
    asm("{ .reg .u64 t; cvta.to.shared.u64 t, %1; cvt.u32.u64 %0, t; }" : "=r"(a) : "l"(p));
    return a;
}
__device__ __forceinline__ void cp16(uint32_t dst, const void* src) {
    asm volatile("cp.async.cg.shared.global [%0], [%1], 16;" :: "r"(dst), "l"(src));
}
#define CP_COMMIT() asm volatile("cp.async.commit_group;" ::: "memory")
#define CP_WAIT(n)  asm volatile("cp.async.wait_group %0;" :: "n"(n) : "memory")

#define LDSM4(r0, r1, r2, r3, addr) \
    asm volatile("ldmatrix.sync.aligned.m8n8.x4.shared.b16 {%0,%1,%2,%3}, [%4];" \
        : "=r"(r0), "=r"(r1), "=r"(r2), "=r"(r3) : "r"(addr))

#define MMA_TF32(c, a, b) \
    asm volatile("mma.sync.aligned.m16n8k8.row.col.f32.tf32.tf32.f32 " \
        "{%0,%1,%2,%3}, {%4,%5,%6,%7}, {%8,%9}, {%0,%1,%2,%3};" \
        : "+f"((c)[0]), "+f"((c)[1]), "+f"((c)[2]), "+f"((c)[3]) \
        : "r"((a)[0]), "r"((a)[1]), "r"((a)[2]), "r"((a)[3]), "r"((b)[0]), "r"((b)[1]))

__device__ __forceinline__ float to_tf32(float v) {
    uint32_t u;
    asm("cvt.rna.tf32.f32 %0, %1;" : "=r"(u) : "f"(v));
    return __uint_as_float(u);
}
__device__ __forceinline__ void cvt_tf32_r(uint32_t& u) {
    asm("cvt.rna.tf32.f32 %0, %0;" : "+r"(u));
}

// Padded K stride (floats): 16 + 4 -> 80B rows, conflict-free ldmatrix
#define LDK 20
// x-residual smem row stride (floats): 128 + 4 pad (16B-aligned rows)
#define LDX 132

// ---------------------------------------------------------------------------
// Precompute partials with K-split x8: z = mode*8 + ks, K window = ks*128..+128
// ---------------------------------------------------------------------------
__global__ __launch_bounds__(256) void precompute_part(
    const float* __restrict__ Mb, const float* __restrict__ Wq,
    const float* __restrict__ Wo)
{
    constexpr int BM = 64, BN = 64, BK = 32;
    __shared__ float As[BK][BM];
    __shared__ float Bs[BK][BN];
    const int mode = blockIdx.z >> 3;
    const int ks   = blockIdx.z & 7;
    const int m0 = blockIdx.y * BM;
    const int n0 = blockIdx.x * BN;
    const int tid = threadIdx.x;
    const int tm = tid >> 4, tn = tid & 15;
    const int kbeg = ks * 128;
    float acc[4][4] = {};

    for (int kb = kbeg; kb < kbeg + 128; kb += BK) {
        {
            int r = tid >> 2, k0 = (tid & 3) * 8;
            float4 v0 = *(const float4*)(Mb + (m0 + r) * EDIM + kb + k0);
            float4 v1 = *(const float4*)(Mb + (m0 + r) * EDIM + kb + k0 + 4);
            As[k0+0][r] = v0.x; As[k0+1][r] = v0.y; As[k0+2][r] = v0.z; As[k0+3][r] = v0.w;
            As[k0+4][r] = v1.x; As[k0+5][r] = v1.y; As[k0+6][r] = v1.z; As[k0+7][r] = v1.w;
        }
        if (mode == 0) {
            int k = tid >> 3, nq = (tid & 7) * 8;
            float4 v0 = *(const float4*)(Wq + (size_t)(kb + k) * EDIM + n0 + nq);
            float4 v1 = *(const float4*)(Wq + (size_t)(kb + k) * EDIM + n0 + nq + 4);
            *(float4*)&Bs[k][nq]     = v0;
            *(float4*)&Bs[k][nq + 4] = v1;
        } else {
            int n = tid >> 2, k0 = (tid & 3) * 8;
            float4 v0 = *(const float4*)(Wo + (size_t)(n0 + n) * EDIM + kb + k0);
            float4 v1 = *(const float4*)(Wo + (size_t)(n0 + n) * EDIM + kb + k0 + 4);
            Bs[k0+0][n] = v0.x; Bs[k0+1][n] = v0.y; Bs[k0+2][n] = v0.z; Bs[k0+3][n] = v0.w;
            Bs[k0+4][n] = v1.x; Bs[k0+5][n] = v1.y; Bs[k0+6][n] = v1.z; Bs[k0+7][n] = v1.w;
        }
        __syncthreads();
        #pragma unroll
        for (int k = 0; k < BK; k++) {
            float a[4], b[4];
            *(float4*)a = *(const float4*)&As[k][tm * 4];
            *(float4*)b = *(const float4*)&Bs[k][tn * 4];
            #pragma unroll
            for (int i = 0; i < 4; i++)
                #pragma unroll
                for (int j = 0; j < 4; j++)
                    acc[i][j] = fmaf(a[i], b[j], acc[i][j]);
        }
        __syncthreads();
    }
    if (mode == 0) {
        float* dst = g_part + (size_t)ks * (MSLOTS * EDIM);
        #pragma unroll
        for (int i = 0; i < 4; i++) {
            int m = m0 + tm * 4 + i;
            *(float4*)(dst + (size_t)m * EDIM + n0 + tn * 4) =
                make_float4(acc[i][0], acc[i][1], acc[i][2], acc[i][3]);
        }
    } else {
        float* dst = g_part + (size_t)(8 + ks) * (MSLOTS * EDIM);
        #pragma unroll
        for (int i = 0; i < 4; i++)
            #pragma unroll
            for (int j = 0; j < 4; j++)
                dst[(size_t)(n0 + tn * 4 + j) * MSLOTS + (m0 + tm * 4 + i)] = acc[i][j];
    }
}

// Sum 8 K-split partials, round to tf32. t < 65536 -> P float4 t; else Rt.
__global__ __launch_bounds__(256) void reduce_pre()
{
    int t = blockIdx.x * 256 + threadIdx.x;      // 0..131071 (float4 index)
    const int NF4 = MSLOTS * EDIM / 4;           // 65536
    int base = (t < NF4) ? 0 : 8;
    int i = (t < NF4) ? t : t - NF4;
    float4 s0v = make_float4(0.f, 0.f, 0.f, 0.f);
    float4 s1v = make_float4(0.f, 0.f, 0.f, 0.f);
    #pragma unroll
    for (int p = 0; p < 8; p += 2) {
        float4 a = ((const float4*)(g_part + (size_t)(base + p)     * (MSLOTS * EDIM)))[i];
        float4 b = ((const float4*)(g_part + (size_t)(base + p + 1) * (MSLOTS * EDIM)))[i];
        s0v.x += a.x; s0v.y += a.y; s0v.z += a.z; s0v.w += a.w;
        s1v.x += b.x; s1v.y += b.y; s1v.z += b.z; s1v.w += b.w;
    }
    float4 o;
    o.x = to_tf32(s0v.x + s1v.x);
    o.y = to_tf32(s0v.y + s1v.y);
    o.z = to_tf32(s0v.z + s1v.z);
    o.w = to_tf32(s0v.w + s1v.w);
    float4* dst = (base == 0) ? (float4*)g_P : (float4*)g_Rt;
    dst[i] = o;
}

__global__ void s0_kernel(const float* __restrict__ Mb, const float* __restrict__ bq)
{
    int m = blockIdx.x;
    int lane = threadIdx.x;
    float s = 0.f;
    #pragma unroll
    for (int c = 0; c < 8; c++) {
        int e = lane * 4 + c * 128;
        float4 mv = *(const float4*)(Mb + (size_t)m * EDIM + e);
        float4 bv = *(const float4*)(bq + e);
        s += mv.x * bv.x + mv.y * bv.y + mv.z * bv.z + mv.w * bv.w;
    }
    #pragma unroll
    for (int o = 16; o; o >>= 1) s += __shfl_xor_sync(0xffffffffu, s, o);
    if (lane == 0) g_s0[m] = s;
}

// ---------------------------------------------------------------------------
// scores + softmax: CTA = 64 rows x 256 slots, K=1024, mma.sync tf32.
// 256 threads = 8 warps in 2x4 grid, warp tile 32x64. 2 CTAs/SM.
// (round-10 structure — FROZEN)
// ---------------------------------------------------------------------------
#define S_AST (64 * LDK * 4)          // 5120
#define S_BST (256 * LDK * 4)         // 20480
#define S_ST  (S_AST + S_BST)         // 25600
#define S_OFF_S0  0
#define S_OFF_RED 1024
#define S_OFF_STG 2048
#define S_SMEM (S_OFF_STG + 4 * S_ST) // 104448

__global__ __launch_bounds__(256, 2) void scores_tc(const float* __restrict__ x)
{
    extern __shared__ char smem[];
    const uint32_t sb = smem_u32(smem);
    const int tid = threadIdx.x;
    const int lane = tid & 31, wid = tid >> 5;
    const int wm = wid >> 2, wn = wid & 3;       // warp grid 2x4
    const int g = lane >> 2, q = lane & 3;
    const int row0 = blockIdx.x * 64;

    if (tid < 64) ((float4*)(smem + S_OFF_S0))[tid] = ((const float4*)g_s0)[tid];

    auto load_stage = [&](int buf, int kb) {
        uint32_t ab = sb + S_OFF_STG + buf * S_ST;
        uint32_t bb = ab + S_AST;
        {   // A: x[row0..row0+63, kb..kb+15]
            int r = tid >> 2, t = tid & 3;
            cp16(ab + (r * LDK + t * 4) * 4, x + (size_t)(row0 + r) * EDIM + kb + t * 4);
        }
        #pragma unroll
        for (int i = 0; i < 4; i++) {   // B: g_P[0..255, kb..kb+15]
            int idx = tid + i * 256;
            int r = idx >> 2, t = idx & 3;
            cp16(bb + (r * LDK + t * 4) * 4, g_P + (size_t)r * EDIM + kb + t * 4);
        }
    };

    float acc[2][8][4] = {};
    #pragma unroll
    for (int p = 0; p < 3; p++) { load_stage(p, p * 16); CP_COMMIT(); }

    for (int s = 0; s < 64; s++) {
        CP_WAIT(2);
        __syncthreads();
        if (s + 3 < 64) load_stage((s + 3) & 3, (s + 3) * 16);
        CP_COMMIT();

        uint32_t aB = sb + S_OFF_STG + (s & 3) * S_ST;
        uint32_t bB = aB + S_AST;
        #pragma unroll
        for (int k8 = 0; k8 < 16; k8 += 8) {
            uint32_t af[2][4], bf[8][2];
            #pragma unroll
            for (int mb = 0; mb < 2; mb++) {
                int row = wm * 32 + mb * 16 + ((lane >> 3) & 1) * 8 + (lane & 7);
                int kof = k8 + ((lane >> 4) << 2);
                LDSM4(af[mb][0], af[mb][1], af[mb][2], af[mb][3],
                      aB + (row * LDK + kof) * 4);
            }
            #pragma unroll
            for (int nb2 = 0; nb2 < 4; nb2++) {
                int n = wn * 64 + nb2 * 16 + ((lane >> 4) & 1) * 8 + (lane & 7);
                int kof = k8 + ((lane >> 3) & 1) * 4;
                LDSM4(bf[nb2*2][0], bf[nb2*2][1], bf[nb2*2+1][0], bf[nb2*2+1][1],
                      bB + (n * LDK + kof) * 4);
            }
            // x is raw fp32 -> round A frags to tf32 (B already rounded)
            #pragma unroll
            for (int mb = 0; mb < 2; mb++)
                #pragma unroll
                for (int i = 0; i < 4; i++) cvt_tf32_r(af[mb][i]);
            #pragma unroll
            for (int mb = 0; mb < 2; mb++)
                #pragma unroll
                for (int nb = 0; nb < 8; nb++)
                    MMA_TF32(acc[mb][nb], af[mb], bf[nb]);
        }
    }

    // ---- softmax epilogue ----
    const float* s0s = (const float*)(smem + S_OFF_S0);
    float* red = (float*)(smem + S_OFF_RED);   // [64 rows][4 col-warps]

    #pragma unroll
    for (int nb = 0; nb < 8; nb++) {
        float2 sp = *(const float2*)(s0s + wn * 64 + nb * 8 + q * 2);
        #pragma unroll
        for (int mb = 0; mb < 2; mb++) {
            acc[mb][nb][0] += sp.x; acc[mb][nb][1] += sp.y;
            acc[mb][nb][2] += sp.x; acc[mb][nb][3] += sp.y;
        }
    }
    float mx[2][2];
    #pragma unroll
    for (int mb = 0; mb < 2; mb++)
        #pragma unroll
        for (int r = 0; r < 2; r++) {
            float m = -1e30f;
            #pragma unroll
            for (int nb = 0; nb < 8; nb++)
                m = fmaxf(m, fmaxf(acc[mb][nb][r*2], acc[mb][nb][r*2+1]));
            m = fmaxf(m, __shfl_xor_sync(0xffffffffu, m, 1));
            m = fmaxf(m, __shfl_xor_sync(0xffffffffu, m, 2));
            if (q == 0) red[(wm * 32 + mb * 16 + g + r * 8) * 4 + wn] = m;
        }
    __syncthreads();
    #pragma unroll
    for (int mb = 0; mb < 2; mb++)
        #pragma unroll
        for (int r = 0; r < 2; r++) {
            int row = wm * 32 + mb * 16 + g + r * 8;
            float4 rv = *(const float4*)(red + row * 4);
            mx[mb][r] = fmaxf(fmaxf(rv.x, rv.y), fmaxf(rv.z, rv.w));
        }
    __syncthreads();
    #pragma unroll
    for (int mb = 0; mb < 2; mb++)
        #pragma unroll
        for (int r = 0; r < 2; r++) {
            float s = 0.f;
            #pragma unroll
            for (int nb = 0; nb < 8; nb++) {
                float e0 = __expf(acc[mb][nb][r*2]   - mx[mb][r]);
                float e1 = __expf(acc[mb][nb][r*2+1] - mx[mb][r]);
                acc[mb][nb][r*2] = e0; acc[mb][nb][r*2+1] = e1;
                s += e0 + e1;
            }
            s += __shfl_xor_sync(0xffffffffu, s, 1);
            s += __shfl_xor_sync(0xffffffffu, s, 2);
            if (q == 0) red[(wm * 32 + mb * 16 + g + r * 8) * 4 + wn] = s;
        }
    __syncthreads();
    #pragma unroll
    for (int mb = 0; mb < 2; mb++)
        #pragma unroll
        for (int r = 0; r < 2; r++) {
            int row = wm * 32 + mb * 16 + g + r * 8;
            float4 rv = *(const float4*)(red + row * 4);
            float inv = 1.f / (rv.x + rv.y + rv.z + rv.w);
            size_t grow = (size_t)(row0 + row);
            #pragma unroll
            for (int nb = 0; nb < 8; nb++) {
                float2 o;
                o.x = to_tf32(acc[mb][nb][r*2]   * inv);
                o.y = to_tf32(acc[mb][nb][r*2+1] * inv);
                *(float2*)(g_w + grow * MSLOTS + wn * 64 + nb * 8 + q * 2) = o;
            }
        }
}

// ---------------------------------------------------------------------------
// out = w @ Rt^T + bo + x: CTA = 128 rows x 128 cols, K=256, mma.sync tf32.
// 256 threads = 8 warps in 2x4 grid, warp tile 64x32. 2 CTAs/SM.
// (round-10 structure — FROZEN; x tile prefetched into freed ring buffers)
// ---------------------------------------------------------------------------
#define O_AST (128 * LDK * 4)         // 10240
#define O_BST (128 * LDK * 4)         // 10240
#define O_ST  (O_AST + O_BST)         // 20480
#define O_SMEM (4 * O_ST)             // 81920; x tile 128*LDX*4=67584 fits

__global__ __launch_bounds__(256, 2) void out_tc(
    const float* __restrict__ x, const float* __restrict__ bo,
    float* __restrict__ out)
{
    extern __shared__ char smem[];
    const uint32_t sb = smem_u32(smem);
    const int tid = threadIdx.x;
    const int lane = tid & 31, wid = tid >> 5;
    const int wm = wid >> 2, wn = wid & 3;       // warp grid 2x4
    const int g = lane >> 2, q = lane & 3;
    const int row0 = blockIdx.y * 128;
    const int col0 = blockIdx.x * 128;

    auto load_stage = [&](int buf, int kb) {
        uint32_t ab = sb + buf * O_ST;
        uint32_t bb = ab + O_AST;
        #pragma unroll
        for (int i = 0; i < 2; i++) {   // A: g_w[row0..+127, kb..kb+15]
            int idx = tid + i * 256;
            int r = idx >> 2, t = idx & 3;
            cp16(ab + (r * LDK + t * 4) * 4, g_w + (size_t)(row0 + r) * MSLOTS + kb + t * 4);
        }
        #pragma unroll
        for (int i = 0; i < 2; i++) {   // B: g_Rt[col0..+127, kb..kb+15]
            int idx = tid + i * 256;
            int r = idx >> 2, t = idx & 3;
            cp16(bb + (r * LDK + t * 4) * 4, g_Rt + (size_t)(col0 + r) * MSLOTS + kb + t * 4);
        }
    };

    // x chunk c: rows 32c..32c+31 of the 128x128 tile into LDX-stride smem.
    // Chunk c's bytes end at (32c+32)*LDX*4 <= (c+1)*O_ST -> each chunk only
    // touches ring buffers 0..c, which are free when it's issued.
    auto load_x_chunk = [&](int c) {
        #pragma unroll
        for (int i = 0; i < 4; i++) {   // 32 rows x 32 cp16
            int idx = tid + i * 256;
            int r = idx >> 5, t = idx & 31;
            cp16(sb + ((c * 32 + r) * LDX + t * 4) * 4,
                 x + (size_t)(row0 + c * 32 + r) * EDIM + col0 + t * 4);
        }
    };

    float acc[4][4][4] = {};
    #pragma unroll
    for (int p = 0; p < 3; p++) { load_stage(p, p * 16); CP_COMMIT(); }

    for (int s = 0; s < 16; s++) {
        CP_WAIT(2);
        __syncthreads();
        if (s + 3 < 16) load_stage((s + 3) & 3, (s + 3) * 16);
        else            load_x_chunk(s - 13);   // s=13,14,15 -> chunks 0,1,2
        CP_COMMIT();

        uint32_t aB = sb + (s & 3) * O_ST;
        uint32_t bB = aB + O_AST;
        #pragma unroll
        for (int k8 = 0; k8 < 16; k8 += 8) {
            uint32_t af[4][4], bf[4][2];
            #pragma unroll
            for (int mb = 0; mb < 4; mb++) {
                int row = wm * 64 + mb * 16 + ((lane >> 3) & 1) * 8 + (lane & 7);
                int kof = k8 + ((lane >> 4) << 2);
                LDSM4(af[mb][0], af[mb][1], af[mb][2], af[mb][3],
                      aB + (row * LDK + kof) * 4);
            }
            #pragma unroll
            for (int nb2 = 0; nb2 < 2; nb2++) {
                int n = wn * 32 + nb2 * 16 + ((lane >> 4) & 1) * 8 + (lane & 7);
                int kof = k8 + ((lane >> 3) & 1) * 4;
                LDSM4(bf[nb2*2][0], bf[nb2*2][1], bf[nb2*2+1][0], bf[nb2*2+1][1],
                      bB + (n * LDK + kof) * 4);
            }
            // both operands pre-rounded to tf32 -> no cvt needed
            #pragma unroll
            for (int mb = 0; mb < 4; mb++)
                #pragma unroll
                for (int nb = 0; nb < 4; nb++)
                    MMA_TF32(acc[mb][nb], af[mb], bf[nb]);
        }
    }

    // buf3 free only after ALL warps finished stage 15's reads
    __syncthreads();
    load_x_chunk(3);
    CP_COMMIT();
    CP_WAIT(0);
    __syncthreads();

    // ---- epilogue: + bo + x (x from smem) ----
    const float* xs = (const float*)smem;
    #pragma unroll
    for (int mb = 0; mb < 4; mb++)
        #pragma unroll
        for (int r = 0; r < 2; r++) {
            int lrow = wm * 64 + mb * 16 + g + r * 8;
            size_t row = (size_t)(row0 + lrow);
            #pragma unroll
            for (int nb = 0; nb < 4; nb++) {
                int lcol = wn * 32 + nb * 8 + q * 2;
                float2 xv = *(const float2*)(xs + lrow * LDX + lcol);
                float2 bv = *(const float2*)(bo + col0 + lcol);
                float2 o;
                o.x = acc[mb][nb][r*2]   + bv.x + xv.x;
                o.y = acc[mb][nb][r*2+1] + bv.y + xv.y;
                *(float2*)(out + row * EDIM + col0 + lcol) = o;
            }
        }
}

// ---------------------------------------------------------------------------
// Launch
// ---------------------------------------------------------------------------
extern "C" void kernel_launch(void* const* d_in, const int* in_sizes, int n_in,
                              void* d_out, int out_size)
{
    (void)in_sizes; (void)n_in; (void)out_size;
    const float* x  = (const float*)d_in[0];
    const float* Mb = (const float*)d_in[1];
    const float* Wq = (const float*)d_in[2];
    const float* bq = (const float*)d_in[3];
    const float* Wo = (const float*)d_in[4];
    const float* bo = (const float*)d_in[5];
    float* out = (float*)d_out;

    cudaFuncSetAttribute(scores_tc, cudaFuncAttributeMaxDynamicSharedMemorySize, S_SMEM);
    cudaFuncSetAttribute(out_tc,    cudaFuncAttributeMaxDynamicSharedMemorySize, O_SMEM);

    precompute_part<<<dim3(EDIM / 64, MSLOTS / 64, 16), 256>>>(Mb, Wq, Wo);
    reduce_pre<<<512, 256>>>();
    s0_kernel<<<MSLOTS, 32>>>(Mb, bq);
    scores_tc<<<NROWS / 64, 256, S_SMEM>>>(x);
    out_tc<<<dim3(EDIM / 128, NROWS / 128), 256, O_SMEM>>>(x, bo, out);
}